// round 3
// baseline (speedup 1.0000x reference)
#include <cuda_runtime.h>
#include <math.h>

// Problem constants
#define MM       2048           // patches
#define NC       4              // compartments
#define NSTEPS   128
#define BETA_F   0.25f
#define TRAJ_ELEMS (NSTEPS * MM * (NC + 1))   // 1310720

// Launch geometry: 128 persistent blocks, 16 rows of R each, 256 threads
// (8 warps x 2 rows/warp). 1 block/SM via smem footprint => co-residency
// guaranteed on 148/152-SM GB300, so the software grid barrier cannot deadlock.
#define NBLK     128
#define ROWS     16
#define NTHREADS 256

// SMEM: R tile (16*2048 f32) + x vector (2048 f32) + ntot (16 f32) + 16 doubles
#define SMEM_BYTES ((ROWS * MM + MM + 16) * 4 + 16 * 8)

// -------- persistent device state (re-initialized every launch) --------
__device__ float        g_x[MM];            // rho[:,0] (phase-A input vector)
__device__ float        g_p[MM];            // infect_prob (phase-B input vector)
__device__ float        g_part[NBLK * MM];  // per-block column partial sums (ntot)
__device__ double       g_bsum[NBLK];       // per-block |traj| sums (agreement)
__device__ unsigned int g_bar_in  = 0;      // monotonic arrival counter
__device__ unsigned int g_bar_gen = 0;      // monotonic generation counter

// Monotonic-counter grid barrier. Invariant across launches:
// after generation g completes, g_bar_in == g * NBLK. Each launch reads the
// current generation before its first arrival, so graph replays are safe.
__device__ __forceinline__ void gridsync(unsigned int &gen) {
    __syncthreads();
    if (threadIdx.x == 0) {
        __threadfence();                                   // publish writes (release)
        unsigned int a = atomicAdd(&g_bar_in, 1u);
        if (a == gen * (unsigned)NBLK + (unsigned)(NBLK - 1)) {
            atomicAdd(&g_bar_gen, 1u);                     // last arriver releases
        } else {
            while (*((volatile unsigned int*)&g_bar_gen) == gen) __nanosleep(64);
        }
        gen++;
    }
    __syncthreads();
}

__global__ void __launch_bounds__(NTHREADS)
metasim_kernel(const float* __restrict__ Rg,
               const float* __restrict__ Tg,
               const float* __restrict__ rho0,
               float* __restrict__ out,
               int out_size)
{
    extern __shared__ float smem[];
    float*  Rs     = smem;                 // [ROWS][MM]
    float*  xs     = Rs + ROWS * MM;       // [MM]
    float*  ntot_s = xs + MM;              // [ROWS]
    double* dsum   = (double*)(ntot_s + 16); // [16], 8B-aligned (offset 139328)

    const int tid     = threadIdx.x;
    const int blk     = blockIdx.x;
    const int w       = tid >> 5;
    const int lane    = tid & 31;
    const int rowbase = blk * ROWS;

    unsigned int gen = 0;
    if (tid == 0) gen = *((volatile unsigned int*)&g_bar_gen);  // stable pre-barrier

    // ---- load this block's 16 rows of R into SMEM (once) ----
    {
        const float4* Rg4 = (const float4*)Rg + (size_t)rowbase * (MM / 4);
        float4* Rs4 = (float4*)Rs;
        #pragma unroll 4
        for (int k = tid; k < ROWS * MM / 4; k += NTHREADS) Rs4[k] = Rg4[k];
    }

    // ---- T (4x4) into registers ----
    float Tr[16];
    #pragma unroll
    for (int i = 0; i < 16; i++) Tr[i] = Tg[i];

    // ---- per-lane rho state: lane 0 -> row 2w, lane 1 -> row 2w+1 ----
    const int myrow = rowbase + 2 * w + lane;   // meaningful for lane < 2
    float r0 = 0.f, r1 = 0.f, r2 = 0.f, r3 = 0.f, kk = 0.f;
    if (lane < 2) {
        r0 = rho0[myrow * 4 + 0];
        r1 = rho0[myrow * 4 + 1];
        r2 = rho0[myrow * 4 + 2];
        r3 = rho0[myrow * 4 + 3];
        __stcg(&g_x[myrow], r0);                // initial x = rho0[:,0]
    }
    __syncthreads();                            // Rs ready for column sums

    // ---- deterministic ntot: per-block column partials (no float atomics) ----
    for (int c = tid; c < MM; c += NTHREADS) {
        float s = 0.f;
        #pragma unroll
        for (int r = 0; r < ROWS; r++) s += Rs[r * MM + c];
        __stcg(&g_part[blk * MM + c], s);
    }

    gridsync(gen);                              // partials + g_x visible

    // ntot for own 16 columns (== own row indices), fixed summation order
    if (tid < ROWS) {
        const int c = rowbase + tid;
        float s = 0.f;
        for (int bb = 0; bb < NBLK; bb++) s += __ldcg(&g_part[bb * MM + c]);
        ntot_s[tid] = s;
    }
    __syncthreads();
    if (lane < 2) kk = -BETA_F / ntot_s[2 * w + lane];

    const float4* Rw0 = (const float4*)(Rs + (2 * w) * MM);
    const float4* Rw1 = (const float4*)(Rs + (2 * w + 1) * MM);
    float4* xs4 = (float4*)xs;

    double dAcc = 0.0;

    for (int t = 0; t < NSTEPS; t++) {
        // ================= Phase A: frac = R @ x, p = 1 - exp(-beta*frac/ntot)
        {
            const float4* gx4 = (const float4*)g_x;
            #pragma unroll
            for (int k = tid; k < MM / 4; k += NTHREADS) xs4[k] = __ldcg(gx4 + k);
        }
        __syncthreads();

        float a0 = 0.f, a1 = 0.f;
        #pragma unroll
        for (int j = 0; j < 16; j++) {
            const int c = j * 32 + lane;
            const float4 xv = xs4[c];
            const float4 u = Rw0[c];
            const float4 v = Rw1[c];
            a0 += u.x * xv.x + u.y * xv.y + u.z * xv.z + u.w * xv.w;
            a1 += v.x * xv.x + v.y * xv.y + v.z * xv.z + v.w * xv.w;
        }
        #pragma unroll
        for (int o = 16; o; o >>= 1) {
            a0 += __shfl_xor_sync(0xffffffffu, a0, o);
            a1 += __shfl_xor_sync(0xffffffffu, a1, o);
        }
        if (lane < 2) {
            const float fr = (lane == 0) ? a0 : a1;
            __stcg(&g_p[myrow], 1.0f - expf(kk * fr));
        }
        gridsync(gen);

        // ================= Phase B: nw = R @ p, compartment update, traj out
        {
            const float4* gp4 = (const float4*)g_p;
            #pragma unroll
            for (int k = tid; k < MM / 4; k += NTHREADS) xs4[k] = __ldcg(gp4 + k);
        }
        __syncthreads();

        float b0 = 0.f, b1 = 0.f;
        #pragma unroll
        for (int j = 0; j < 16; j++) {
            const int c = j * 32 + lane;
            const float4 xv = xs4[c];
            const float4 u = Rw0[c];
            const float4 v = Rw1[c];
            b0 += u.x * xv.x + u.y * xv.y + u.z * xv.z + u.w * xv.w;
            b1 += v.x * xv.x + v.y * xv.y + v.z * xv.z + v.w * xv.w;
        }
        #pragma unroll
        for (int o = 16; o; o >>= 1) {
            b0 += __shfl_xor_sync(0xffffffffu, b0, o);
            b1 += __shfl_xor_sync(0xffffffffu, b1, o);
        }
        if (lane < 2) {
            const float acc = (lane == 0) ? b0 : b1;
            const float s   = r0 + r1 + r2 + r3;
            const float nw  = (1.0f - s) * acc;
            float n0 = r0 * Tr[0] + r1 * Tr[4] + r2 * Tr[8]  + r3 * Tr[12] + nw;
            float n1 = r0 * Tr[1] + r1 * Tr[5] + r2 * Tr[9]  + r3 * Tr[13];
            float n2 = r0 * Tr[2] + r1 * Tr[6] + r2 * Tr[10] + r3 * Tr[14];
            float n3 = r0 * Tr[3] + r1 * Tr[7] + r2 * Tr[11] + r3 * Tr[15];
            n0 = fminf(fmaxf(n0, 0.0f), 1e10f);
            n1 = fminf(fmaxf(n1, 0.0f), 1e10f);
            n2 = fminf(fmaxf(n2, 0.0f), 1e10f);
            n3 = fminf(fmaxf(n3, 0.0f), 1e10f);
            r0 = n0; r1 = n1; r2 = n2; r3 = n3;
            __stcg(&g_x[myrow], n0);                      // next step's x

            const float S = 1.0f - (n0 + n1 + n2 + n3);   // AddSusceptibleLayer
            float* o = out + ((size_t)t * MM + myrow) * (NC + 1);
            o[0] = S; o[1] = n0; o[2] = n1; o[3] = n2; o[4] = n3;
            dAcc += (double)(fabsf(S) + fabsf(n0) + fabsf(n1) + fabsf(n2) + fabsf(n3));
        }
        gridsync(gen);
    }

    // ---- agreement = mean(|traj|), fully deterministic reduction ----
    if (lane < 2) dsum[2 * w + lane] = dAcc;
    __syncthreads();
    if (tid == 0) {
        double s = 0.0;
        for (int i = 0; i < 16; i++) s += dsum[i];
        __stcg(&g_bsum[blk], s);
    }
    gridsync(gen);
    if (blk == 0 && tid == 0 && out_size > TRAJ_ELEMS) {
        double s = 0.0;
        for (int i = 0; i < NBLK; i++) s += __ldcg(&g_bsum[i]);
        out[TRAJ_ELEMS] = (float)(s / (double)TRAJ_ELEMS);
    }
}

extern "C" void kernel_launch(void* const* d_in, const int* in_sizes, int n_in,
                              void* d_out, int out_size)
{
    // Identify inputs by element count (robust to metadata ordering):
    // R: 2048*2048, T: 4*4, rho0: 2048*4
    const float* R    = nullptr;
    const float* Tm   = nullptr;
    const float* rho0 = nullptr;
    for (int i = 0; i < n_in; i++) {
        if      (in_sizes[i] == MM * MM) R    = (const float*)d_in[i];
        else if (in_sizes[i] == NC * NC) Tm   = (const float*)d_in[i];
        else if (in_sizes[i] == MM * NC) rho0 = (const float*)d_in[i];
    }
    // Fallback to declared order if sizes were ambiguous
    if (!R    && n_in > 0) R    = (const float*)d_in[0];
    if (!Tm   && n_in > 1) Tm   = (const float*)d_in[1];
    if (!rho0 && n_in > 2) rho0 = (const float*)d_in[2];

    cudaFuncSetAttribute(metasim_kernel,
                         cudaFuncAttributeMaxDynamicSharedMemorySize,
                         SMEM_BYTES);

    metasim_kernel<<<NBLK, NTHREADS, SMEM_BYTES>>>(R, Tm, rho0,
                                                   (float*)d_out, out_size);
}